// round 3
// baseline (speedup 1.0000x reference)
#include <cuda_runtime.h>

#define BATCH 16384

typedef unsigned long long u64;
typedef unsigned int       u32;

// Scratch (device globals: allocation-free rule)
__device__ float  g_hT[64 * BATCH];     // layer0 output transposed [o][b]
__device__ float4 g_dup0[4096 * 6];     // layer0 params, duplicated pairs
__device__ float4 g_dup1[1024 * 6];     // layer1 params, duplicated pairs
__device__ float  g_b3s0[64];           // sum_i b3 per output o, layer0
__device__ float  g_b3s1[16];           // layer1

__device__ __forceinline__ u64 fma2(u64 a, u64 b, u64 c) {
    u64 d;
    asm("fma.rn.f32x2 %0, %1, %2, %3;" : "=l"(d) : "l"(a), "l"(b), "l"(c));
    return d;
}
__device__ __forceinline__ u64 pk(float a, float b) {
    return (u64)__float_as_uint(a) | ((u64)__float_as_uint(b) << 32);
}
__device__ __forceinline__ float flo(u64 v) { return __uint_as_float((u32)v); }
__device__ __forceinline__ float fhi(u64 v) { return __uint_as_float((u32)(v >> 32)); }
__device__ __forceinline__ u64 relu2(u64 v) {
    return pk(fmaxf(flo(v), 0.0f), fmaxf(fhi(v), 0.0f));
}

// Build duplicated-pair param buffers + b3 column sums.
// Blocks 0..39: 5120 subnets (4096 layer0 + 1024 layer1), one per thread.
// Blocks 40..59: 80 warps, one b3 column-sum each (64 layer0 + 16 layer1).
__global__ void prep(const float* __restrict__ l0W1, const float* __restrict__ l0b1,
                     const float* __restrict__ l0W2, const float* __restrict__ l0b2,
                     const float* __restrict__ l0W3, const float* __restrict__ l0b3,
                     const float* __restrict__ l1W1, const float* __restrict__ l1b1,
                     const float* __restrict__ l1W2, const float* __restrict__ l1b2,
                     const float* __restrict__ l1W3, const float* __restrict__ l1b3)
{
    int blk = blockIdx.x, tid = threadIdx.x;
    if (blk < 40) {
        int t = blk * 128 + tid;
        bool isL0 = t < 4096;
        int n = isL0 ? t : t - 4096;
        const float* W1 = isL0 ? l0W1 : l1W1;
        const float* b1 = isL0 ? l0b1 : l1b1;
        const float* W2 = isL0 ? l0W2 : l1W2;
        const float* b2 = isL0 ? l0b2 : l1b2;
        const float* W3 = isL0 ? l0W3 : l1W3;
        float4* q = (isL0 ? g_dup0 : g_dup1) + (size_t)n * 6;
        float w1a = W1[2*n], w1b = W1[2*n+1];
        float b1a = b1[2*n], b1b = b1[2*n+1];
        float w200 = W2[4*n], w201 = W2[4*n+1], w210 = W2[4*n+2], w211 = W2[4*n+3];
        float b2a = b2[2*n], b2b = b2[2*n+1];
        float w3a = W3[2*n], w3b = W3[2*n+1];
        q[0] = make_float4(w1a, w1a, w1b, w1b);
        q[1] = make_float4(b1a, b1a, b1b, b1b);
        q[2] = make_float4(w200, w200, w201, w201);
        q[3] = make_float4(w210, w210, w211, w211);
        q[4] = make_float4(b2a, b2a, b2b, b2b);
        q[5] = make_float4(w3a, w3a, w3b, w3b);
    } else {
        int wg = (blk - 40) * 4 + (tid >> 5);
        int lane = tid & 31;
        if (wg < 80) {
            bool isL0 = wg < 64;
            int o = isL0 ? wg : wg - 64;
            int OUT = isL0 ? 64 : 16;
            const float* b3 = isL0 ? l0b3 : l1b3;
            float s = b3[lane * OUT + o] + b3[(lane + 32) * OUT + o];
#pragma unroll
            for (int m = 16; m; m >>= 1) s += __shfl_xor_sync(0xffffffffu, s, m);
            if (lane == 0) (isL0 ? g_b3s0 : g_b3s1)[o] = s;
        }
    }
}

// One KAN layer. 256 threads = 8 warps; warp w owns output column o = o0+w.
// Each lane processes 4 batch elements as two f32x2 pairs. Params fetched per
// (i,o) as 6 uniform LDG.128 from the duplicated buffer (1 L1 line each).
// MODE 0: x read from a conflict-free smem tile (staged from row-major x),
//         output written transposed to g_hT (coalesced float4).
// MODE 1: x read directly from g_hT rows (coalesced float4), output [b][o].
template <int OUT, int MODE>
__global__ __launch_bounds__(256) void kan_layer(
    const float* __restrict__ xin, float* __restrict__ dout)
{
    constexpr int PITCH = 132;
    __shared__ float xt[(MODE == 0) ? 64 * PITCH : 4];

    int tid  = threadIdx.x;
    int lane = tid & 31;
    int o    = blockIdx.y * 8 + (tid >> 5);
    int B0   = blockIdx.x * 128;

    if (MODE == 0) {
        // Stage x[B0..B0+127][0..63] -> xt[i][bb]; coalesced LDG.32 (consecutive i),
        // STS.128 with distinct banks across the 8-lane phase.
        int i  = tid & 63;
        int bq = tid >> 6;
#pragma unroll
        for (int p = 0; p < 8; p++) {
            int bb = p * 16 + bq * 4;
            float v0 = xin[(size_t)(B0 + bb + 0) * 64 + i];
            float v1 = xin[(size_t)(B0 + bb + 1) * 64 + i];
            float v2 = xin[(size_t)(B0 + bb + 2) * 64 + i];
            float v3 = xin[(size_t)(B0 + bb + 3) * 64 + i];
            *(float4*)&xt[i * PITCH + bb] = make_float4(v0, v1, v2, v3);
        }
        __syncthreads();
    }

    const float* b3s = (MODE == 0) ? g_b3s0 : g_b3s1;
    float s3 = b3s[o];
    u64 sp = pk(s3, s3);
    u64 acc00 = sp, acc01 = 0, acc10 = sp, acc11 = 0;

    const float4* q = ((MODE == 0) ? g_dup0 : g_dup1) + (size_t)o * 6;
    const float* xg = g_hT + (size_t)B0 + lane * 4;   // MODE 1 source

#pragma unroll 2
    for (int i = 0; i < 64; i++) {
        float4 a0 = q[0], a1 = q[1], a2 = q[2], a3 = q[3], a4 = q[4], a5 = q[5];
        float4 xq;
        if (MODE == 0) xq = *(const float4*)&xt[i * PITCH + lane * 4];
        else           xq = *(const float4*)(xg + (size_t)i * BATCH);

        u64 xv0 = pk(xq.x, xq.y), xv1 = pk(xq.z, xq.w);
        u64 w1a = pk(a0.x, a0.y), w1b = pk(a0.z, a0.w);
        u64 b1a = pk(a1.x, a1.y), b1b = pk(a1.z, a1.w);
        u64 w20 = pk(a2.x, a2.y), w21 = pk(a2.z, a2.w);
        u64 w22 = pk(a3.x, a3.y), w23 = pk(a3.z, a3.w);
        u64 b2a = pk(a4.x, a4.y), b2b = pk(a4.z, a4.w);
        u64 w3a = pk(a5.x, a5.y), w3b = pk(a5.z, a5.w);

        u64 r1 = relu2(fma2(w1a, xv0, b1a));
        u64 r2 = relu2(fma2(w1b, xv0, b1b));
        u64 ga = relu2(fma2(w20, r1, fma2(w21, r2, b2a)));
        u64 gb = relu2(fma2(w22, r1, fma2(w23, r2, b2b)));
        acc00 = fma2(w3a, ga, acc00);
        acc01 = fma2(w3b, gb, acc01);

        r1 = relu2(fma2(w1a, xv1, b1a));
        r2 = relu2(fma2(w1b, xv1, b1b));
        ga = relu2(fma2(w20, r1, fma2(w21, r2, b2a)));
        gb = relu2(fma2(w22, r1, fma2(w23, r2, b2b)));
        acc10 = fma2(w3a, ga, acc10);
        acc11 = fma2(w3b, gb, acc11);

        q += OUT * 6;
    }

    float f0 = flo(acc00) + flo(acc01);
    float f1 = fhi(acc00) + fhi(acc01);
    float f2 = flo(acc10) + flo(acc11);
    float f3 = fhi(acc10) + fhi(acc11);

    if (MODE == 0) {
        *(float4*)&g_hT[(size_t)o * BATCH + B0 + lane * 4] =
            make_float4(f0, f1, f2, f3);
    } else {
        int b = B0 + lane * 4;
        dout[(size_t)(b + 0) * OUT + o] = f0;
        dout[(size_t)(b + 1) * OUT + o] = f1;
        dout[(size_t)(b + 2) * OUT + o] = f2;
        dout[(size_t)(b + 3) * OUT + o] = f3;
    }
}

extern "C" void kernel_launch(void* const* d_in, const int* in_sizes, int n_in,
                              void* d_out, int out_size)
{
    const float* x    = (const float*)d_in[0];
    const float* l0W1 = (const float*)d_in[1];
    const float* l0b1 = (const float*)d_in[2];
    const float* l0W2 = (const float*)d_in[3];
    const float* l0b2 = (const float*)d_in[4];
    const float* l0W3 = (const float*)d_in[5];
    const float* l0b3 = (const float*)d_in[6];
    const float* l1W1 = (const float*)d_in[7];
    const float* l1b1 = (const float*)d_in[8];
    const float* l1W2 = (const float*)d_in[9];
    const float* l1b2 = (const float*)d_in[10];
    const float* l1W3 = (const float*)d_in[11];
    const float* l1b3 = (const float*)d_in[12];
    float* out = (float*)d_out;

    prep<<<60, 128>>>(l0W1, l0b1, l0W2, l0b2, l0W3, l0b3,
                      l1W1, l1b1, l1W2, l1b2, l1W3, l1b3);
    kan_layer<64, 0><<<dim3(BATCH / 128, 8), 256>>>(x, nullptr);
    kan_layer<16, 1><<<dim3(BATCH / 128, 2), 256>>>(nullptr, out);
}